// round 5
// baseline (speedup 1.0000x reference)
#include <cuda_runtime.h>

// Conditional encoding: 2-layer LSTM (B=1024, T=256, D=50, H=64) + MLP head.
// x@Wih^T+bias precomputed per vocab entry (32.8MB/layer L2 table).
// Recurrence: 256 CTAs x 4 rows, 2 CTAs/SM. Warp = 8 channels x 4 gate types;
// per-gate activation applied in-register after the dot, 4x4 shfl transpose,
// one combine per lane, ONE barrier per step, c/gather state in registers.

#define BB   1024
#define TT   256
#define DD   50
#define HH   64
#define GG   256   // 4*H
#define VV   32004
#define BT   4     // batch rows per recurrent CTA
#define NCTA 256
#define NTHR 256
#define HP   72    // padded h row stride (72 mod 32 = 8 banks -> conflict-free)
#define VB   1001  // ceil(32004/32)

typedef unsigned long long u64;

__device__ float g_tab0[(long)VV * GG];   // layer-1 gate-x table (32.8 MB)
__device__ float g_tab1[(long)VV * GG];   // layer-2 gate-x table

__device__ __forceinline__ u64 pk2(float a, float b) {
    u64 r; asm("mov.b64 %0, {%1, %2};" : "=l"(r) : "f"(a), "f"(b)); return r;
}
__device__ __forceinline__ u64 ffma2(u64 a, u64 b, u64 c) {
    u64 d; asm("fma.rn.f32x2 %0, %1, %2, %3;" : "=l"(d) : "l"(a), "l"(b), "l"(c)); return d;
}
__device__ __forceinline__ float pairsum(u64 a) {
    float x, y; asm("mov.b64 {%0, %1}, %2;" : "=f"(x), "=f"(y) : "l"(a)); return x + y;
}
__device__ __forceinline__ float tanha(float x) {
    float y; asm("tanh.approx.f32 %0, %1;" : "=f"(y) : "f"(x)); return y;
}
__device__ __forceinline__ float siga(float x) {
    return fmaf(0.5f, tanha(0.5f * x), 0.5f);
}

// ---------------- precompute GEMM: tab[v][g] = emb[v].Wih[g] + bih[g]+bhh[g] ----
__global__ void __launch_bounds__(256) precompute_kernel(
    const float* __restrict__ emb,
    const float* __restrict__ WihA, const float* __restrict__ biA, const float* __restrict__ bhA,
    const float* __restrict__ WihB, const float* __restrict__ biB, const float* __restrict__ bhB)
{
    const int layer = blockIdx.x >= VB;
    const int vb    = layer ? blockIdx.x - VB : blockIdx.x;
    const float* Wih = layer ? WihB : WihA;
    const float* bi  = layer ? biB  : biA;
    const float* bh  = layer ? bhB  : bhA;
    float* tab = layer ? g_tab1 : g_tab0;

    __shared__ float xs[32][DD];
    __shared__ __align__(8) float wsT[25][GG];
    __shared__ __align__(8) float bsh[GG];

    const int tid = threadIdx.x;
    const int v0  = vb * 32;

    for (int idx = tid; idx < 32 * DD; idx += 256) {
        int v = idx / DD, k = idx - v * DD;
        int vg = v0 + v;
        xs[v][k] = (vg < VV) ? emb[(long)vg * DD + k] : 0.f;
    }
    bsh[tid] = bi[tid] + bh[tid];
    __syncthreads();

    const int gg = tid & 31;    // gate-pair lane: pairs 2*(gg+32j)
    const int vq = tid >> 5;    // v-group: rows vq*4 .. +3

    u64 acc[4][4];
    #pragma unroll
    for (int j = 0; j < 4; ++j) {
        u64 bp = *(const u64*)&bsh[2 * (gg + 32 * j)];
        #pragma unroll
        for (int v = 0; v < 4; ++v) acc[v][j] = bp;
    }

    for (int kc = 0; kc < 2; ++kc) {
        __syncthreads();
        {
            const float* wp = Wih + (long)tid * DD + kc * 25;
            #pragma unroll
            for (int k = 0; k < 25; ++k) wsT[k][tid] = wp[k];
        }
        __syncthreads();
        #pragma unroll
        for (int k = 0; k < 25; ++k) {
            u64 wv[4];
            #pragma unroll
            for (int j = 0; j < 4; ++j)
                wv[j] = *(const u64*)&wsT[k][2 * (gg + 32 * j)];
            #pragma unroll
            for (int v = 0; v < 4; ++v) {
                float xv = xs[vq * 4 + v][kc * 25 + k];
                u64 xp = pk2(xv, xv);
                #pragma unroll
                for (int j = 0; j < 4; ++j) acc[v][j] = ffma2(wv[j], xp, acc[v][j]);
            }
        }
    }

    #pragma unroll
    for (int v = 0; v < 4; ++v) {
        int vg = v0 + vq * 4 + v;
        if (vg < VV) {
            #pragma unroll
            for (int j = 0; j < 4; ++j)
                *(u64*)(tab + (long)vg * GG + 2 * (gg + 32 * j)) = acc[v][j];
        }
    }
}

// ---------------- recurrent kernel ----------------
__global__ void __launch_bounds__(NTHR, 2) cond_enc_kernel(
    const int*   __restrict__ s1,   const int*   __restrict__ s2,
    const int*   __restrict__ len1, const int*   __restrict__ len2,
    const float* __restrict__ Whh1,
    const float* __restrict__ Whh2,
    const float* __restrict__ Wl1,  const float* __restrict__ bl1,
    const float* __restrict__ Wl2,  const float* __restrict__ bl2,
    float* __restrict__ out)
{
    __shared__ int   toksh[BT][TT];                      // 4 KB
    __shared__ __align__(16) float hA[BT][HP];
    __shared__ __align__(16) float hB[BT][HP];
    __shared__ float ghh[BT][HH];
    __shared__ float l1sh[BT][128];

    const int tid = threadIdx.x;
    const int b0  = blockIdx.x * BT;
    const int w   = tid >> 5;
    const int l   = tid & 31;
    const int ch  = w * 8 + (l & 7);     // channel 0..63
    const int gt  = l >> 3;              // gate type 0..3 (i,f,g,o); also my row
    const int grow = gt * HH + ch;       // this lane's gate row of Whh/tab
    const bool isg = (gt != 2);          // i,f,o -> sigmoid; g -> tanh

    u64   wreg[32];                      // Whh row pairs
    float gx[BT], pf[BT];
    float cmy;                           // c-state for (row=gt, ch)
    float mgh = 0.f, mgc = 0.f;          // gathered h,c (registers)
    int   glmy;

    for (int phase = 0; phase < 2; ++phase) {
        const int*   sent = phase ? s2   : s1;
        const int*   slen = phase ? len2 : len1;
        const float* Whh  = phase ? Whh2 : Whh1;
        const float* tab  = phase ? g_tab1 : g_tab0;

        {
            const float4* hp = (const float4*)(Whh + (long)grow * HH);
            #pragma unroll
            for (int q = 0; q < 16; ++q) {
                float4 wv = hp[q];
                wreg[2 * q]     = pk2(wv.x, wv.y);
                wreg[2 * q + 1] = pk2(wv.z, wv.w);
            }
        }
        for (int idx = tid; idx < BT * TT; idx += NTHR) {
            int r = idx >> 8, t = idx & 255;
            toksh[r][t] = sent[(b0 + r) * TT + t];
        }
        glmy = slen[(b0 + gt) * HH + ch];
        cmy  = (phase == 0) ? 0.f : mgc;
        hA[gt][ch] = (phase == 0) ? 0.f : mgh;
        __syncthreads();

        #pragma unroll
        for (int r = 0; r < BT; ++r)
            gx[r] = __ldg(&tab[(long)toksh[r][0] * GG + grow]);

        // one LSTM step: read HRD, write HWR, current time TCUR, prefetch TNX
        #define LSTEP(HRD, HWR, TCUR, TNX)                                     \
        {                                                                      \
            _Pragma("unroll")                                                  \
            for (int r = 0; r < BT; ++r)                                       \
                pf[r] = __ldg(&tab[(long)toksh[r][(TNX)] * GG + grow]);        \
            u64 a0[BT], a1[BT];                                                \
            _Pragma("unroll")                                                  \
            for (int r = 0; r < BT; ++r) { a0[r] = pk2(gx[r], 0.f); a1[r] = 0ULL; } \
            _Pragma("unroll")                                                  \
            for (int k = 0; k < 16; ++k) {                                     \
                _Pragma("unroll")                                              \
                for (int r = 0; r < BT; ++r) {                                 \
                    ulonglong2 hv = *(const ulonglong2*)&HRD[r][4 * k];        \
                    a0[r] = ffma2(wreg[2 * k],     hv.x, a0[r]);               \
                    a1[r] = ffma2(wreg[2 * k + 1], hv.y, a1[r]);               \
                }                                                              \
            }                                                                  \
            float act[BT];                                                     \
            _Pragma("unroll")                                                  \
            for (int r = 0; r < BT; ++r) {                                     \
                float p  = pairsum(a0[r]) + pairsum(a1[r]);                    \
                float q  = isg ? 0.5f * p : p;                                 \
                float tq = tanha(q);                                           \
                act[r]   = isg ? fmaf(0.5f, tq, 0.5f) : tq;                    \
                gx[r]    = pf[r];                                              \
            }                                                                  \
            /* 4x4 transpose across gate lanes (rows<->gates) */               \
            {                                                                  \
                float ta = (gt & 2) ? act[0] : act[2];                         \
                float tb = (gt & 2) ? act[1] : act[3];                         \
                ta = __shfl_xor_sync(0xffffffffu, ta, 16);                     \
                tb = __shfl_xor_sync(0xffffffffu, tb, 16);                     \
                if (gt & 2) { act[0] = ta; act[1] = tb; }                      \
                else        { act[2] = ta; act[3] = tb; }                      \
                ta = (gt & 1) ? act[0] : act[1];                               \
                tb = (gt & 1) ? act[2] : act[3];                               \
                ta = __shfl_xor_sync(0xffffffffu, ta, 8);                      \
                tb = __shfl_xor_sync(0xffffffffu, tb, 8);                      \
                if (gt & 1) { act[0] = ta; act[2] = tb; }                      \
                else        { act[1] = ta; act[3] = tb; }                      \
            }                                                                  \
            /* combine for (row=gt, ch): i=act0 f=act1 g=act2 o=act3 */        \
            {                                                                  \
                float cn = fmaf(act[1], cmy, act[0] * act[2]);                 \
                float hn = act[3] * tanha(cn);                                 \
                cmy = cn;                                                      \
                if (glmy == (TCUR)) { mgh = hn; mgc = cn; }                    \
                HWR[gt][ch] = hn;                                              \
            }                                                                  \
            __syncthreads();                                                   \
        }

        #pragma unroll 1
        for (int t = 0; t < TT; t += 2) {
            LSTEP(hA, hB, t,     t + 1)
            LSTEP(hB, hA, t + 1, (t + 2 < TT) ? t + 2 : TT - 1)
        }
        #undef LSTEP
    }

    // publish gathered h for the head
    ghh[gt][ch] = mgh;
    __syncthreads();

    // ================= MLP head =================
    #pragma unroll
    for (int q = 0; q < 2; ++q) {
        int p = tid + NTHR * q;                      // 512 = 4 rows x 128
        int r = p >> 7, j = p & 127;
        float acc = bl1[j];
        const float* wr = Wl1 + j * HH;
        #pragma unroll
        for (int k = 0; k < HH; ++k) acc = fmaf(ghh[r][k], wr[k], acc);
        l1sh[r][j] = tanha(acc);
    }
    __syncthreads();
    if (tid < BT * 4) {
        int r = tid >> 2, kk = tid & 3;
        float acc = bl2[kk];
        const float* wr = Wl2 + kk * 128;
        #pragma unroll
        for (int k = 0; k < 128; ++k) acc = fmaf(l1sh[r][k], wr[k], acc);
        out[(b0 + r) * 4 + kk] = acc;
    }
}

extern "C" void kernel_launch(void* const* d_in, const int* in_sizes, int n_in,
                              void* d_out, int out_size)
{
    const int*   s1   = (const int*)  d_in[0];
    const int*   s2   = (const int*)  d_in[1];
    const int*   len1 = (const int*)  d_in[2];
    const int*   len2 = (const int*)  d_in[3];
    // d_in[4], d_in[5] (s1_s, s2_s) unused by the reference model
    const float* emb  = (const float*)d_in[6];
    const float* Wih1 = (const float*)d_in[7];
    const float* Whh1 = (const float*)d_in[8];
    const float* bih1 = (const float*)d_in[9];
    const float* bhh1 = (const float*)d_in[10];
    const float* Wih2 = (const float*)d_in[11];
    const float* Whh2 = (const float*)d_in[12];
    const float* bih2 = (const float*)d_in[13];
    const float* bhh2 = (const float*)d_in[14];
    const float* Wl1  = (const float*)d_in[15];
    const float* bl1  = (const float*)d_in[16];
    const float* Wl2  = (const float*)d_in[17];
    const float* bl2  = (const float*)d_in[18];
    float* out = (float*)d_out;

    precompute_kernel<<<2 * VB, 256>>>(emb, Wih1, bih1, bhh1, Wih2, bih2, bhh2);
    cond_enc_kernel<<<NCTA, NTHR>>>(s1, s2, len1, len2,
                                    Whh1, Whh2, Wl1, bl1, Wl2, bl2, out);
}